// round 1
// baseline (speedup 1.0000x reference)
#include <cuda_runtime.h>

// Problem constants
#define B_   2
#define S_   2048
#define E_   1024
#define H_   16
#define D_   64
#define BH_  (B_*H_)      // 32
#define TOK_ (B_*S_)      // 4096

// ---------------------------------------------------------------------------
// Static device scratch (allocation inside kernel_launch is forbidden).
// ---------------------------------------------------------------------------
__device__ float d_Qp[B_*H_*S_*D_];          // 16.8 MB, [B,H,S,D]
__device__ float d_Kp[B_*H_*S_*D_];
__device__ float d_Vp[B_*H_*S_*D_];
__device__ float d_attn[B_*H_*S_*S_];        // 536.9 MB, [B,H,Sq,Sk] (probs, then mixed in-place)
__device__ float d_ctx[B_*S_*E_];            // 16.8 MB, [B,S,E]
__device__ float d_mixsm[H_*H_];             // softmaxed head-mixing [G,H]

// ---------------------------------------------------------------------------
// 0) softmax of the 16x16 head-mixing matrix (rows over source heads)
// ---------------------------------------------------------------------------
__global__ void mix_softmax_kernel(const float* __restrict__ hm) {
    int g = threadIdx.x;
    if (g >= H_) return;
    float m = -1e30f;
    #pragma unroll
    for (int h = 0; h < H_; h++) m = fmaxf(m, hm[g*H_ + h]);
    float e[H_]; float s = 0.f;
    #pragma unroll
    for (int h = 0; h < H_; h++) { e[h] = expf(hm[g*H_ + h] - m); s += e[h]; }
    float inv = 1.f / s;
    #pragma unroll
    for (int h = 0; h < H_; h++) d_mixsm[g*H_ + h] = e[h] * inv;
}

// ---------------------------------------------------------------------------
// 1) SGEMM 128x128x8, 8x8 per thread. A [M=4096,K=1024] rm, W [K,N=1024] rm.
//    mode 0: C row-major [M,N] (+bias)   -> used for output projection
//    mode 1: write [B,H,S,D] layout      -> used for Q/K/V projections
// ---------------------------------------------------------------------------
__global__ __launch_bounds__(256) void sgemm_proj(
    const float* __restrict__ A, const float* __restrict__ W,
    const float* __restrict__ bias, float* __restrict__ out, int mode)
{
    const int K = E_, N = E_;
    __shared__ __align__(16) float As[8][128];
    __shared__ __align__(16) float Bs[8][128];
    const int tid = threadIdx.x;
    const int bm = blockIdx.y * 128;
    const int bn = blockIdx.x * 128;
    const int tx = tid & 15, ty = tid >> 4;

    float acc[8][8];
    #pragma unroll
    for (int i = 0; i < 8; i++)
        #pragma unroll
        for (int j = 0; j < 8; j++) acc[i][j] = 0.f;

    const int aRow = tid >> 1, aC = (tid & 1) * 4;   // A tile: 128x8
    const int bRow = tid >> 5, bC = (tid & 31) * 4;  // W tile: 8x128

    for (int k0 = 0; k0 < K; k0 += 8) {
        float4 av = *(const float4*)&A[(size_t)(bm + aRow)*K + k0 + aC];
        As[aC+0][aRow] = av.x; As[aC+1][aRow] = av.y;
        As[aC+2][aRow] = av.z; As[aC+3][aRow] = av.w;
        *(float4*)&Bs[bRow][bC] = *(const float4*)&W[(size_t)(k0 + bRow)*N + bn + bC];
        __syncthreads();
        #pragma unroll
        for (int kk = 0; kk < 8; kk++) {
            float a[8], b[8];
            *(float4*)&a[0] = *(float4*)&As[kk][ty*8];
            *(float4*)&a[4] = *(float4*)&As[kk][ty*8 + 4];
            *(float4*)&b[0] = *(float4*)&Bs[kk][tx*8];
            *(float4*)&b[4] = *(float4*)&Bs[kk][tx*8 + 4];
            #pragma unroll
            for (int i = 0; i < 8; i++)
                #pragma unroll
                for (int j = 0; j < 8; j++) acc[i][j] += a[i]*b[j];
        }
        __syncthreads();
    }

    #pragma unroll
    for (int i = 0; i < 8; i++) {
        int r = bm + ty*8 + i;
        #pragma unroll
        for (int j = 0; j < 8; j++) {
            int c = bn + tx*8 + j;
            float v = acc[i][j] + bias[c];
            if (mode == 0) {
                out[(size_t)r*N + c] = v;
            } else {
                int b = r / S_, s = r & (S_-1);
                int h = c / D_, d = c & (D_-1);
                out[(((size_t)b*H_ + h)*S_ + s)*D_ + d] = v;
            }
        }
    }
}

// ---------------------------------------------------------------------------
// 2) scores = Q @ K^T / 8, batched over (b,h). NT GEMM, 128x128, Kd=64.
// ---------------------------------------------------------------------------
__global__ __launch_bounds__(256) void attn_scores_kernel()
{
    const int bh = blockIdx.z;
    const float* Q  = d_Qp + (size_t)bh * S_ * D_;
    const float* Kp = d_Kp + (size_t)bh * S_ * D_;
    float* out = d_attn + (size_t)bh * S_ * S_;

    __shared__ __align__(16) float As[8][128];
    __shared__ __align__(16) float Bs[8][128];
    const int tid = threadIdx.x;
    const int bm = blockIdx.y * 128;  // q tile
    const int bn = blockIdx.x * 128;  // k tile
    const int tx = tid & 15, ty = tid >> 4;

    float acc[8][8];
    #pragma unroll
    for (int i = 0; i < 8; i++)
        #pragma unroll
        for (int j = 0; j < 8; j++) acc[i][j] = 0.f;

    const int r = tid >> 1, c4 = (tid & 1) * 4;

    for (int k0 = 0; k0 < D_; k0 += 8) {
        float4 av = *(const float4*)&Q [(size_t)(bm + r)*D_ + k0 + c4];
        float4 bv = *(const float4*)&Kp[(size_t)(bn + r)*D_ + k0 + c4];
        As[c4+0][r] = av.x; As[c4+1][r] = av.y; As[c4+2][r] = av.z; As[c4+3][r] = av.w;
        Bs[c4+0][r] = bv.x; Bs[c4+1][r] = bv.y; Bs[c4+2][r] = bv.z; Bs[c4+3][r] = bv.w;
        __syncthreads();
        #pragma unroll
        for (int kk = 0; kk < 8; kk++) {
            float a[8], b[8];
            *(float4*)&a[0] = *(float4*)&As[kk][ty*8];
            *(float4*)&a[4] = *(float4*)&As[kk][ty*8 + 4];
            *(float4*)&b[0] = *(float4*)&Bs[kk][tx*8];
            *(float4*)&b[4] = *(float4*)&Bs[kk][tx*8 + 4];
            #pragma unroll
            for (int i = 0; i < 8; i++)
                #pragma unroll
                for (int j = 0; j < 8; j++) acc[i][j] += a[i]*b[j];
        }
        __syncthreads();
    }

    #pragma unroll
    for (int i = 0; i < 8; i++) {
        size_t rowBase = (size_t)(bm + ty*8 + i) * S_;
        #pragma unroll
        for (int j = 0; j < 8; j++)
            out[rowBase + bn + tx*8 + j] = acc[i][j] * 0.125f;  // 1/sqrt(64)
    }
}

// ---------------------------------------------------------------------------
// 3) row softmax over 2048 k's. One block per (b,h,q) row; values in regs.
// ---------------------------------------------------------------------------
__global__ __launch_bounds__(256) void softmax_rows_kernel()
{
    __shared__ float red[256];
    float* row = d_attn + (size_t)blockIdx.x * S_;
    const int t = threadIdx.x;

    float4 v0 = ((float4*)row)[t];
    float4 v1 = ((float4*)row)[t + 256];

    float m = fmaxf(fmaxf(fmaxf(v0.x, v0.y), fmaxf(v0.z, v0.w)),
                    fmaxf(fmaxf(v1.x, v1.y), fmaxf(v1.z, v1.w)));
    red[t] = m; __syncthreads();
    #pragma unroll
    for (int s = 128; s > 0; s >>= 1) {
        if (t < s) red[t] = fmaxf(red[t], red[t + s]);
        __syncthreads();
    }
    m = red[0]; __syncthreads();

    v0.x = expf(v0.x - m); v0.y = expf(v0.y - m); v0.z = expf(v0.z - m); v0.w = expf(v0.w - m);
    v1.x = expf(v1.x - m); v1.y = expf(v1.y - m); v1.z = expf(v1.z - m); v1.w = expf(v1.w - m);
    float s8 = v0.x + v0.y + v0.z + v0.w + v1.x + v1.y + v1.z + v1.w;

    red[t] = s8; __syncthreads();
    #pragma unroll
    for (int s = 128; s > 0; s >>= 1) {
        if (t < s) red[t] += red[t + s];
        __syncthreads();
    }
    float inv = 1.f / red[0];

    v0.x *= inv; v0.y *= inv; v0.z *= inv; v0.w *= inv;
    v1.x *= inv; v1.y *= inv; v1.z *= inv; v1.w *= inv;
    ((float4*)row)[t]       = v0;
    ((float4*)row)[t + 256] = v1;
}

// ---------------------------------------------------------------------------
// 4) head mixing IN PLACE: for each (b,q,k), mixed[g] = sum_h mixsm[g,h]*p[h].
//    Each thread owns one (b,q,k) across all 16 heads -> no races.
// ---------------------------------------------------------------------------
__global__ __launch_bounds__(256) void head_mix_kernel()
{
    __shared__ float mix[H_*H_];
    if (threadIdx.x < H_*H_) mix[threadIdx.x] = d_mixsm[threadIdx.x];
    __syncthreads();

    const int p = blockIdx.x * 256 + threadIdx.x;   // < B*S*S = 2^23
    const int b = p >> 22;                          // S*S = 2^22
    const int r = p & ((1 << 22) - 1);
    float* base = d_attn + (size_t)b * H_ * (S_*(size_t)S_) + r;

    float a[H_];
    #pragma unroll
    for (int h = 0; h < H_; h++) a[h] = base[(size_t)h * S_ * S_];

    float o[H_];
    #pragma unroll
    for (int g = 0; g < H_; g++) {
        float acc = 0.f;
        #pragma unroll
        for (int h = 0; h < H_; h++) acc += mix[g*H_ + h] * a[h];
        o[g] = acc;
    }
    #pragma unroll
    for (int g = 0; g < H_; g++) base[(size_t)g * S_ * S_] = o[g];
}

// ---------------------------------------------------------------------------
// 5) ctx = mixed @ V, batched over (b,g). NN GEMM 128x64x16 tiles.
//    Epilogue writes directly to [B,S,E] so the output proj is plain row-major.
// ---------------------------------------------------------------------------
__global__ __launch_bounds__(256) void ctx_gemm_kernel()
{
    const int bg = blockIdx.z;
    const int b = bg >> 4, g = bg & 15;
    const float* Amat = d_attn + (size_t)bg * S_ * S_;   // mixed probs [S,S]
    const float* V    = d_Vp   + (size_t)bg * S_ * D_;   // [S,D]

    __shared__ __align__(16) float As[16][128];
    __shared__ __align__(16) float Bs[16][64];
    const int tid = threadIdx.x;
    const int bm = blockIdx.y * 128;
    const int tx = tid & 15, ty = tid >> 4;   // cols tx*4.., rows ty*8..

    float acc[8][4];
    #pragma unroll
    for (int i = 0; i < 8; i++)
        #pragma unroll
        for (int j = 0; j < 4; j++) acc[i][j] = 0.f;

    for (int k0 = 0; k0 < S_; k0 += 16) {
        #pragma unroll
        for (int i = 0; i < 2; i++) {                    // A tile 128x16
            int l = tid + i*256;
            int r = l >> 2, c4 = (l & 3) * 4;
            float4 av = *(const float4*)&Amat[(size_t)(bm + r)*S_ + k0 + c4];
            As[c4+0][r] = av.x; As[c4+1][r] = av.y;
            As[c4+2][r] = av.z; As[c4+3][r] = av.w;
        }
        {                                                // V tile 16x64
            int r = tid >> 4, c4 = (tid & 15) * 4;
            *(float4*)&Bs[r][c4] = *(const float4*)&V[(size_t)(k0 + r)*D_ + c4];
        }
        __syncthreads();
        #pragma unroll
        for (int kk = 0; kk < 16; kk++) {
            float a[8], bb[4];
            *(float4*)&a[0]  = *(float4*)&As[kk][ty*8];
            *(float4*)&a[4]  = *(float4*)&As[kk][ty*8 + 4];
            *(float4*)&bb[0] = *(float4*)&Bs[kk][tx*4];
            #pragma unroll
            for (int i = 0; i < 8; i++)
                #pragma unroll
                for (int j = 0; j < 4; j++) acc[i][j] += a[i]*bb[j];
        }
        __syncthreads();
    }

    #pragma unroll
    for (int i = 0; i < 8; i++) {
        int q = bm + ty*8 + i;
        #pragma unroll
        for (int j = 0; j < 4; j++) {
            int d = tx*4 + j;
            d_ctx[((size_t)b*S_ + q)*E_ + g*D_ + d] = acc[i][j];
        }
    }
}

// ---------------------------------------------------------------------------
// kernel_launch: graph-capturable sequence on the default stream.
// ---------------------------------------------------------------------------
extern "C" void kernel_launch(void* const* d_in, const int* in_sizes, int n_in,
                              void* d_out, int out_size)
{
    (void)in_sizes; (void)n_in; (void)out_size;
    const float* query = (const float*)d_in[0];
    const float* key_  = (const float*)d_in[1];
    const float* value = (const float*)d_in[2];
    const float* Wq = (const float*)d_in[3];
    const float* bq = (const float*)d_in[4];
    const float* Wk = (const float*)d_in[5];
    const float* bk = (const float*)d_in[6];
    const float* Wv = (const float*)d_in[7];
    const float* bv = (const float*)d_in[8];
    const float* hm = (const float*)d_in[9];
    const float* Wo = (const float*)d_in[10];
    const float* bo = (const float*)d_in[11];
    float* out = (float*)d_out;

    float *Qp, *Kp, *Vp, *Ctx;
    cudaGetSymbolAddress((void**)&Qp,  d_Qp);
    cudaGetSymbolAddress((void**)&Kp,  d_Kp);
    cudaGetSymbolAddress((void**)&Vp,  d_Vp);
    cudaGetSymbolAddress((void**)&Ctx, d_ctx);

    mix_softmax_kernel<<<1, 16>>>(hm);

    dim3 gp(E_/128, TOK_/128);                      // (8, 32)
    sgemm_proj<<<gp, 256>>>(query, Wq, bq, Qp, 1);
    sgemm_proj<<<gp, 256>>>(key_,  Wk, bk, Kp, 1);
    sgemm_proj<<<gp, 256>>>(value, Wv, bv, Vp, 1);

    attn_scores_kernel<<<dim3(S_/128, S_/128, BH_), 256>>>();   // (16,16,32)
    softmax_rows_kernel<<<BH_*S_, 256>>>();                      // 65536 rows
    head_mix_kernel<<<(B_*S_*S_)/256, 256>>>();                  // 32768 blocks
    ctx_gemm_kernel<<<dim3(1, S_/128, B_*H_), 256>>>();          // (1,16,32)

    sgemm_proj<<<gp, 256>>>(Ctx, Wo, bo, out, 0);                // output proj
}